// round 16
// baseline (speedup 1.0000x reference)
#include <cuda_runtime.h>
#include <cuda_fp16.h>
#include <cstdint>
#include <math.h>

constexpr int Bb=64, Tt=12, Nn=1024, Ee=10, Hor=12;
constexpr int ROWS = Nn*Bb;          // 65536
constexpr int NN2  = Nn*Nn;
constexpr int FPK  = 256;            // padded K width of F (3*66=198 -> 256)
constexpr int XTC  = 66*Bb;          // 4224 = Xin^T row count (cols of Xin)
// ROW ORDER: id = b*1024 + n  (batch-major)

// ---------------- device-global scratch ----------------
__device__ __align__(1024) float g_S_enc[2*NN2];
__device__ __align__(1024) float g_S_dec[2*NN2];
__device__ __align__(1024) __half g_Rh[(size_t)ROWS*64];   // r gate, fp16
__device__ __align__(1024) float g_h [(size_t)ROWS*64];
__device__ __align__(1024) float g_go[ROWS];
__device__ __align__(1024) float g_demb [Nn*Bb*Ee];
__device__ __align__(1024) float g_dembT[Bb*Ee*Nn];
__device__ __align__(1024) float g_embpad [Nn*16];
__device__ __align__(1024) float g_embpadT[16*Nn];

__device__ __align__(1024) __half g_Se_hi[2*NN2];
__device__ __align__(1024) __half g_Sd_hi[2*NN2];
__device__ __align__(1024) __half g_XT[(size_t)XTC*Nn];          // [b*66+c][n]
__device__ __align__(1024) __half g_F[(size_t)ROWS*FPK];         // [b*1024+n][256]
__device__ __align__(1024) __half g_Wge[128*FPK];
__device__ __align__(1024) __half g_Wue[64*FPK];
__device__ __align__(1024) __half g_Wgd[128*FPK];
__device__ __align__(1024) __half g_Wud[64*FPK];

// HW MUFU.TANH (sm_75+)
__device__ __forceinline__ float tanh_fast(float x){
    float y; asm("tanh.approx.f32 %0, %1;" : "=f"(y) : "f"(x)); return y;
}
__device__ __forceinline__ float sigmoid_fast(float x){
    return fmaf(0.5f, tanh_fast(0.5f * x), 0.5f);
}

__device__ __forceinline__ uint32_t smem_u32(const void* p){
    uint32_t a;
    asm("{ .reg .u64 t; cvta.to.shared.u64 t, %1; cvt.u32.u64 %0, t; }" : "=r"(a) : "l"(p));
    return a;
}
__device__ __forceinline__ void cp_async16(uint32_t dst, const void* src){
    asm volatile("cp.async.cg.shared.global [%0], [%1], 16;" :: "r"(dst), "l"(src));
}
__device__ __forceinline__ void cp_commit(){ asm volatile("cp.async.commit_group;"); }
template <int N>
__device__ __forceinline__ void cp_wait(){ asm volatile("cp.async.wait_group %0;" :: "n"(N)); }

__device__ __forceinline__ void ldsm_x4(uint32_t* r, uint32_t addr){
    asm volatile("ldmatrix.sync.aligned.m8n8.x4.shared.b16 {%0,%1,%2,%3}, [%4];"
        : "=r"(r[0]), "=r"(r[1]), "=r"(r[2]), "=r"(r[3]) : "r"(addr));
}
__device__ __forceinline__ void mma16816(float* c, const uint32_t* a, const uint32_t* b){
    asm volatile("mma.sync.aligned.m16n8k16.row.col.f32.f16.f16.f32 "
        "{%0,%1,%2,%3}, {%4,%5,%6,%7}, {%8,%9}, {%0,%1,%2,%3};"
        : "+f"(c[0]), "+f"(c[1]), "+f"(c[2]), "+f"(c[3])
        : "r"(a[0]), "r"(a[1]), "r"(a[2]), "r"(a[3]), "r"(b[0]), "r"(b[1]));
}

// ---------------- fp16 HMMA GEMM -----------------------
// D[M rows, N=BN per block] = A(M x segK) @ B^T, fp32 accumulate.
// A rows = output rows (lda); B rows = output COLUMNS, K-major (ldb).
// BK=64. Warp grid (THR/64)m x 2n; per-warp tile 32x(BN/2). Row id = b*1024+n.
// Diffusion: BM=256, THR=512, NSTG=3 (1 CTA/SM, 16 warps, 166KB smem).
// MLPs: BM=128, THR=256, NSTG=2 + cp.async prefetch of epilogue operands.
// EPI 0: diffusion -> fp16 scatter into g_F
// EPI 1: gate: z=sig(+bias), c<64 -> z*h into g_XT + g_F; c>=64 -> g_Rh
// EPI 2: update: hc=tanh(+bias); hn = r*h + (1-r)*hc -> g_h, g_XT, g_F
template <int BM, int BN, int EPI, int NSTG, int THR>
__global__ void __launch_bounds__(THR, THR == 512 ? 1 : 2) mma_gemm(
    const __half* __restrict__ A, const __half* __restrict__ B,
    int lda, int ldb, int segK, const float* __restrict__ bias)
{
    constexpr int LDS = 72;                // 64 + 8 pad (half elems)
    constexpr int NT = BN / 16;
    constexpr int A_IT = BM * 8 / THR;     // cp.async iters for A tile
    constexpr int B_IT = BN * 8 / THR;
    constexpr uint32_t STG_BYTES = (uint32_t)(BM + BN) * LDS * 2u;
    extern __shared__ __align__(16) char sm[];
    const uint32_t sm0 = smem_u32(sm);

    const int tid = threadIdx.x, lane = tid & 31, wid = tid >> 5;
    const int wm = wid >> 1, wn = wid & 1;
    const int m0 = blockIdx.y * BM, n0 = blockIdx.x * BN;
    const int KT = segK >> 6;

    float acc[2][NT][4];
#pragma unroll
    for (int i = 0; i < 2; i++)
#pragma unroll
        for (int j = 0; j < NT; j++)
#pragma unroll
            for (int e = 0; e < 4; e++) acc[i][j][e] = 0.0f;

    const uint32_t aOff = (((uint32_t)(wm*32 + (lane & 15))) * LDS + ((lane >> 4) << 3)) * 2u;
    const uint32_t bOff = (uint32_t)BM * LDS * 2u
        + (((uint32_t)(wn*(BN/2) + (lane & 7) + ((lane >> 4) << 3))) * LDS
           + (((lane >> 3) & 1) << 3)) * 2u;

    auto load_tile = [&](int kt, int stg) {
        const uint32_t sA = sm0 + (uint32_t)stg * STG_BYTES;
        const uint32_t sB = sA + (uint32_t)BM * LDS * 2u;
        const char* Ag = (const char*)(A + (size_t)m0 * lda + kt * 64);
        const char* Bg = (const char*)(B + (size_t)n0 * ldb + kt * 64);
#pragma unroll
        for (int it = 0; it < A_IT; it++) {
            int id = it * THR + tid;
            int r = id >> 3, c = id & 7;
            cp_async16(sA + (uint32_t)r*144u + (uint32_t)c*16u,
                       Ag + (size_t)r * ((size_t)lda*2) + c*16);
        }
#pragma unroll
        for (int it = 0; it < B_IT; it++) {
            int id = it * THR + tid;
            int r = id >> 3, c = id & 7;
            cp_async16(sB + (uint32_t)r*144u + (uint32_t)c*16u,
                       Bg + (size_t)r * ((size_t)ldb*2) + c*16);
        }
        cp_commit();
    };

    auto compute = [&](int stg) {
        const uint32_t sbase = sm0 + (uint32_t)stg * STG_BYTES;
        const uint32_t aBase = sbase + aOff;
        const uint32_t bBase = sbase + bOff;
#pragma unroll
        for (int ks = 0; ks < 4; ks++) {
            uint32_t a[2][4];
            ldsm_x4(a[0], aBase + (uint32_t)ks*32u);
            ldsm_x4(a[1], aBase + 16u*LDS*2u + (uint32_t)ks*32u);
            uint32_t b[NT/2][4];
#pragma unroll
            for (int p = 0; p < NT/2; p++)
                ldsm_x4(b[p], bBase + (uint32_t)p*16u*LDS*2u + (uint32_t)ks*32u);
#pragma unroll
            for (int mt = 0; mt < 2; mt++)
#pragma unroll
                for (int nt = 0; nt < NT; nt++)
                    mma16816(acc[mt][nt], a[mt], &b[nt >> 1][(nt & 1) * 2]);
        }
    };

    if (NSTG == 3) {
        load_tile(0, 0);
        if (KT > 1) load_tile(1, 1);
        int stg = 0;
        for (int kt = 0; kt < KT; kt++) {
            if (kt + 1 < KT) cp_wait<1>(); else cp_wait<0>();
            __syncthreads();
            if (kt + 2 < KT) load_tile(kt + 2, (kt + 2) % 3);
            compute(stg);
            if (++stg == 3) stg = 0;
        }
    } else {
        // prefetch epilogue operands under the mainloop (THR==256 path)
        if (EPI >= 1) {
#pragma unroll
            for (int it = 0; it < 8; it++) {
                int idx = (it << 8) + tid;
                cp_async16(sm0 + 2u*STG_BYTES + (uint32_t)idx*16u,
                           (const char*)g_h + (size_t)m0*256 + (size_t)idx*16);
            }
            if (EPI == 2) {
#pragma unroll
                for (int it = 0; it < 4; it++) {
                    int idx = (it << 8) + tid;
                    cp_async16(sm0 + 2u*STG_BYTES + 32768u + (uint32_t)idx*16u,
                               (const char*)g_Rh + (size_t)m0*128 + (size_t)idx*16);
                }
            }
            cp_commit();
        }
        load_tile(0, 0);
        for (int kt = 0; kt < KT; kt++) {
            cp_wait<0>();
            __syncthreads();
            if (kt + 1 < KT) load_tile(kt + 1, (kt + 1) & 1);
            compute(kt & 1);
        }
    }

    // ---------------- epilogue (paired half2/float2; batch-major rows) -------
    const float*  s_hf = reinterpret_cast<const float*>(sm + 2u*STG_BYTES);
    const __half* s_rh = reinterpret_cast<const __half*>(sm + 2u*STG_BYTES + 32768u);
    const int rbase = m0 + wm*32 + (lane >> 2);
    const int cb = n0 + wn*(BN/2) + ((lane & 3) << 1);   // even
#pragma unroll
    for (int mt = 0; mt < 2; mt++) {
#pragma unroll
        for (int nt = 0; nt < NT; nt++) {
#pragma unroll
            for (int ep = 0; ep < 2; ep++) {
                const int row = rbase + mt*16 + ep*8;
                const int lrow = row - m0;
                const int col0 = cb + nt*8;              // even
                const float v0 = acc[mt][nt][ep*2 + 0];
                const float v1 = acc[mt][nt][ep*2 + 1];
                if (EPI == 0) {
                    const int kk = row >> 10, n = row & 1023;
                    const int b = col0 / 66, c = col0 - b * 66;
                    const size_t off = (size_t)((b << 10) + n) * FPK + (kk + 1) * 66 + c;
                    *reinterpret_cast<__half2*>(&g_F[off]) = __floats2half2_rn(v0, v1);
                } else if (EPI == 1) {
                    const int id = row, b = row >> 10, n = row & 1023;
                    if (col0 < 64) {                      // warp-uniform (wn==0)
                        const float2 hp = *reinterpret_cast<const float2*>(
                            &s_hf[lrow * 64 + col0]);
                        const float zh0 = sigmoid_fast(v0 + bias[col0])     * hp.x;
                        const float zh1 = sigmoid_fast(v1 + bias[col0 + 1]) * hp.y;
                        const __half h0 = __float2half_rn(zh0);
                        const __half h1 = __float2half_rn(zh1);
                        g_XT[((size_t)(b * 66 + 2 + col0) << 10) + n] = h0;
                        g_XT[((size_t)(b * 66 + 3 + col0) << 10) + n] = h1;
                        *reinterpret_cast<__half2*>(&g_F[((size_t)id << 8) + 2 + col0]) =
                            __halves2half2(h0, h1);
                    } else {                              // warp-uniform (wn==1)
                        const float r0 = sigmoid_fast(v0 + bias[col0]);
                        const float r1 = sigmoid_fast(v1 + bias[col0 + 1]);
                        *reinterpret_cast<__half2*>(&g_Rh[(size_t)id * 64 + (col0 - 64)]) =
                            __floats2half2_rn(r0, r1);
                    }
                } else {
                    const int id = row, b = row >> 10, n = row & 1023;
                    const float2 hp = *reinterpret_cast<const float2*>(
                        &s_hf[lrow * 64 + col0]);
                    const __half2 rh = *reinterpret_cast<const __half2*>(
                        &s_rh[lrow * 64 + col0]);
                    const float2 rp = __half22float2(rh);
                    const float hc0 = tanh_fast(v0 + bias[col0]);
                    const float hc1 = tanh_fast(v1 + bias[col0 + 1]);
                    const float hn0 = rp.x * hp.x + (1.0f - rp.x) * hc0;
                    const float hn1 = rp.y * hp.y + (1.0f - rp.y) * hc1;
                    *reinterpret_cast<float2*>(&g_h[(size_t)id * 64 + col0]) =
                        make_float2(hn0, hn1);
                    const __half h0 = __float2half_rn(hn0);
                    const __half h1 = __float2half_rn(hn1);
                    g_XT[((size_t)(b * 66 + 2 + col0) << 10) + n] = h0;
                    g_XT[((size_t)(b * 66 + 3 + col0) << 10) + n] = h1;
                    *reinterpret_cast<__half2*>(&g_F[((size_t)id << 8) + 2 + col0]) =
                        __halves2half2(h0, h1);
                }
            }
        }
    }
}

// ---------------- fp32 SGEMM (setup only) ----------------
__global__ void __launch_bounds__(256) sgemm32(
    const float* __restrict__ A, const float* __restrict__ B,
    float* __restrict__ C, int M, int N, int K)
{
    constexpr int BM = 128, BN = 64, BK = 16;
    __shared__ __align__(16) float As_[BK][BM];
    __shared__ __align__(16) float Bs_[BK][BN];
    const int tid = threadIdx.x;
    const int tx = tid & 15, ty = tid >> 4;
    const int m0 = blockIdx.y * BM, n0 = blockIdx.x * BN;
    float acc[8][4];
#pragma unroll
    for (int i = 0; i < 8; i++)
#pragma unroll
        for (int jj = 0; jj < 4; jj++) acc[i][jj] = 0.0f;
    const int arow0 = tid >> 2, acol0 = (tid & 3) * 4;
    const int brow = tid >> 4, bcol = (tid & 15) * 4;
    for (int kt = 0; kt < K; kt += BK) {
#pragma unroll
        for (int i = 0; i < 2; i++) {
            int r = arow0 + i * 64;
            float4 v = *reinterpret_cast<const float4*>(A + (size_t)(m0 + r) * K + kt + acol0);
            As_[acol0+0][r]=v.x; As_[acol0+1][r]=v.y; As_[acol0+2][r]=v.z; As_[acol0+3][r]=v.w;
        }
        float4 bv = *reinterpret_cast<const float4*>(B + (size_t)(kt + brow) * N + n0 + bcol);
        *reinterpret_cast<float4*>(&Bs_[brow][bcol]) = bv;
        __syncthreads();
#pragma unroll
        for (int k = 0; k < BK; k++) {
            float4 a0 = *reinterpret_cast<const float4*>(&As_[k][ty*8]);
            float4 a1 = *reinterpret_cast<const float4*>(&As_[k][ty*8+4]);
            float4 b0 = *reinterpret_cast<const float4*>(&Bs_[k][tx*4]);
            float am[8]={a0.x,a0.y,a0.z,a0.w,a1.x,a1.y,a1.z,a1.w};
            float bn[4]={b0.x,b0.y,b0.z,b0.w};
#pragma unroll
            for (int i = 0; i < 8; i++)
#pragma unroll
                for (int jj = 0; jj < 4; jj++) acc[i][jj] = fmaf(am[i], bn[jj], acc[i][jj]);
        }
        __syncthreads();
    }
#pragma unroll
    for (int i = 0; i < 8; i++) {
        float4 v = make_float4(acc[i][0], acc[i][1], acc[i][2], acc[i][3]);
        *reinterpret_cast<float4*>(C + (size_t)(m0 + ty*8 + i) * N + n0 + tx*4) = v;
    }
}

// ---------------- elementwise helpers (id = b*1024 + n) ----------------
__global__ void k_zero_state() {
    int idx = blockIdx.x * blockDim.x + threadIdx.x;
    if (idx >= ROWS * 64) return;
    int id = idx >> 6, i = idx & 63;
    int b = id >> 10, n = id & 1023;
    g_h[idx] = 0.0f;
    g_XT[((size_t)(b * 66 + 2 + i) << 10) + n] = __float2half_rn(0.0f);
    g_F[((size_t)id << 8) + 2 + i] = __float2half_rn(0.0f);
}
__global__ void k_tohalf(const float* __restrict__ s, __half* __restrict__ hi, size_t n) {
    size_t i = (size_t)blockIdx.x * blockDim.x + threadIdx.x;
    if (i >= n) return;
    hi[i] = __float2half_rn(s[i]);
}
__global__ void k_pad_emb(const float* __restrict__ emb) {
    int idx = blockIdx.x * blockDim.x + threadIdx.x;
    if (idx >= Nn * 16) return;
    int n = idx >> 4, j = idx & 15;
    g_embpad[idx] = (j < Ee) ? emb[n * Ee + j] : 0.0f;
}
__global__ void k_transpose(const float* __restrict__ in, float* __restrict__ out,
                            int R, int C) {
    int idx = blockIdx.x * blockDim.x + threadIdx.x;
    if (idx >= R * C) return;
    int r = idx / C, c = idx - r * C;
    out[c * R + r] = in[idx];
}
template <bool ENC>
__global__ void k_pad_w_t(const float* __restrict__ src, __half* __restrict__ dst,
                          int nout) {
    int idx = blockIdx.x * blockDim.x + threadIdx.x;
    if (idx >= nout * FPK) return;
    int n = idx >> 8, f = idx & 255;
    float v = 0.0f;
    if (f < 198) {
        int k = f / 66, c = f - k * 66;
        if (ENC) {
            if (c == 0) v = src[(k * 65) * nout + n];
            else if (c >= 2) v = src[(k * 65 + c - 1) * nout + n];
        } else {
            v = src[f * nout + n];
        }
    }
    dst[idx] = __float2half_rn(v);
}
__global__ void k_relu_softmax(float* __restrict__ S) {
    int row = blockIdx.x;
    float* p = S + (size_t)row * Nn;
    int t = threadIdx.x;
    float v[4];
#pragma unroll
    for (int i = 0; i < 4; i++) { float x = p[t + i*256]; v[i] = x > 0.0f ? x : 0.0f; }
    __shared__ float red[256];
    float m = fmaxf(fmaxf(v[0], v[1]), fmaxf(v[2], v[3]));
    red[t] = m; __syncthreads();
    for (int s = 128; s > 0; s >>= 1) { if (t < s) red[t] = fmaxf(red[t], red[t+s]); __syncthreads(); }
    m = red[0]; __syncthreads();
    float e[4], sum = 0.0f;
#pragma unroll
    for (int i = 0; i < 4; i++) { e[i] = expf(v[i] - m); sum += e[i]; }
    red[t] = sum; __syncthreads();
    for (int s = 128; s > 0; s >>= 1) { if (t < s) red[t] += red[t+s]; __syncthreads(); }
    float inv = 1.0f / red[0];
#pragma unroll
    for (int i = 0; i < 4; i++) p[t + i*256] = e[i] * inv;
}
__global__ void k_cheb(float* __restrict__ P) {
    int idx = blockIdx.x * blockDim.x + threadIdx.x;
    if (idx >= NN2) return;
    int r = idx >> 10, c = idx & 1023;
    P[idx] = 2.0f * P[idx] - (r == c ? 1.0f : 0.0f);
}
__global__ void k_set_x_enc(const float* __restrict__ x, int t) {
    int id = blockIdx.x * blockDim.x + threadIdx.x;
    if (id >= ROWS) return;
    int b = id >> 10, n = id & 1023;
    float xv = x[((size_t)b * Tt + t) * Nn + n];
    __half xh = __float2half_rn(xv);
    g_XT[((size_t)(b * 66) << 10) + n] = xh;
    g_F[(size_t)id << 8] = xh;
}
__global__ void k_set_xy_dec(const float* __restrict__ ycov, int t) {
    int id = blockIdx.x * blockDim.x + threadIdx.x;
    if (id >= ROWS) return;
    int b = id >> 10, n = id & 1023;
    float gv = g_go[id];
    float yv = ycov[((size_t)b * Hor + t) * Nn + n];
    __half gh = __float2half_rn(gv);
    __half yh = __float2half_rn(yv);
    g_XT[((size_t)(b * 66) << 10) + n] = gh;
    g_XT[((size_t)(b * 66 + 1) << 10) + n] = yh;
    size_t fo = (size_t)id << 8;
    g_F[fo] = gh;
    g_F[fo + 1] = yh;
}
__global__ void k_demb(const float* __restrict__ fce) {
    int idx = blockIdx.x * blockDim.x + threadIdx.x;
    if (idx >= ROWS * Ee) return;
    int id = idx / Ee, e = idx - id * Ee;
    int b = id >> 10, n = id & 1023;
    const float* hr = g_h + (size_t)id * 64;
    float s = 0.0f;
#pragma unroll
    for (int h = 0; h < 64; h++) s = fmaf(hr[h], fce[h * Ee + e], s);
    g_demb[(size_t)n * (Bb * Ee) + b * Ee + e] = s;
}
__global__ void k_init_go(const float* __restrict__ x) {
    int id = blockIdx.x * blockDim.x + threadIdx.x;
    if (id >= ROWS) return;
    int b = id >> 10, n = id & 1023;
    g_go[id] = x[((size_t)b * Tt + (Tt - 1)) * Nn + n];
}
__global__ void k_proj_out(const float* __restrict__ pw, const float* __restrict__ pb,
                           float* __restrict__ out, int t) {
    int id = blockIdx.x * blockDim.x + threadIdx.x;
    if (id >= ROWS) return;
    int b = id >> 10, n = id & 1023;
    const float* hr = g_h + (size_t)id * 64;
    float s = pb[0];
#pragma unroll
    for (int i = 0; i < 64; i++) s = fmaf(hr[i], pw[i], s);
    g_go[id] = s;
    out[((size_t)b * Hor + t) * Nn + n] = s;
}

// ---------------- orchestration ----------------
extern "C" void kernel_launch(void* const* d_in, const int* in_sizes, int n_in,
                              void* d_out, int out_size) {
    const float* x    = (const float*)d_in[0];
    const float* ycov = (const float*)d_in[1];
    const float* emb  = (const float*)d_in[2];
    const float* fce  = (const float*)d_in[3];
    const float* egw  = (const float*)d_in[4];
    const float* egb  = (const float*)d_in[5];
    const float* euw  = (const float*)d_in[6];
    const float* eub  = (const float*)d_in[7];
    const float* dgw  = (const float*)d_in[8];
    const float* dgb  = (const float*)d_in[9];
    const float* duw  = (const float*)d_in[10];
    const float* dub  = (const float*)d_in[11];
    const float* pw   = (const float*)d_in[12];
    const float* pb   = (const float*)d_in[13];
    float* out = (float*)d_out;

    float *pSe, *pSd, *pDemb, *pDembT, *pEp, *pEpT;
    __half *pSeh, *pSdh, *pX, *pF, *pWge, *pWue, *pWgd, *pWud;
    cudaGetSymbolAddress((void**)&pSe, g_S_enc);
    cudaGetSymbolAddress((void**)&pSd, g_S_dec);
    cudaGetSymbolAddress((void**)&pDemb, g_demb);
    cudaGetSymbolAddress((void**)&pDembT, g_dembT);
    cudaGetSymbolAddress((void**)&pEp, g_embpad);
    cudaGetSymbolAddress((void**)&pEpT, g_embpadT);
    cudaGetSymbolAddress((void**)&pSeh, g_Se_hi);
    cudaGetSymbolAddress((void**)&pSdh, g_Sd_hi);
    cudaGetSymbolAddress((void**)&pX, g_XT);
    cudaGetSymbolAddress((void**)&pF, g_F);
    cudaGetSymbolAddress((void**)&pWge, g_Wge);
    cudaGetSymbolAddress((void**)&pWue, g_Wue);
    cudaGetSymbolAddress((void**)&pWgd, g_Wgd);
    cudaGetSymbolAddress((void**)&pWud, g_Wud);

    constexpr int SMEM_DIFF = 3 * (256 + 128) * 72 * 2;                 // 165888
    constexpr int SMEM_GATE = 2 * (128 + 128) * 72 * 2 + 32768;         // 106496
    constexpr int SMEM_UPD  = 2 * (128 + 64) * 72 * 2 + 32768 + 16384;  // 104448
    cudaFuncSetAttribute((const void*)mma_gemm<256,128,0,3,512>,
                         cudaFuncAttributeMaxDynamicSharedMemorySize, SMEM_DIFF);
    cudaFuncSetAttribute((const void*)mma_gemm<128,128,1,2,256>,
                         cudaFuncAttributeMaxDynamicSharedMemorySize, SMEM_GATE);
    cudaFuncSetAttribute((const void*)mma_gemm<128,64,2,2,256>,
                         cudaFuncAttributeMaxDynamicSharedMemorySize, SMEM_UPD);

    // ---- setup; launch index 3 (0-based) == diffusion GEMM for ncu
    k_zero_state<<<16384, 256>>>();                                                     // 0
    k_pad_w_t<true><<<(128 * FPK + 255) / 256, 256>>>(egw, pWge, 128);                  // 1
    k_pad_w_t<true><<<(64 * FPK + 255) / 256, 256>>>(euw, pWue, 64);                    // 2
    // ncu target: real-shape diffusion (deterministic inputs; F cols 66..197
    // overwritten by the real t=0 diffusion before any consumer)
    mma_gemm<256,128,0,3,512><<<dim3(33, 8), 512, SMEM_DIFF>>>(pSeh, pX, Nn, Nn, 1024, nullptr); // 3
    k_pad_emb<<<64, 256>>>(emb);
    k_transpose<<<64, 256>>>(pEp, pEpT, Nn, 16);
    sgemm32<<<dim3(16, 8), 256>>>(pEp, pEpT, pSe, Nn, Nn, 16);
    k_relu_softmax<<<Nn, 256>>>(pSe);
    sgemm32<<<dim3(16, 8), 256>>>(pSe, pSe, pSe + NN2, Nn, Nn, Nn);
    k_cheb<<<NN2 / 256, 256>>>(pSe + NN2);
    k_tohalf<<<2 * NN2 / 256, 256>>>(pSe, pSeh, (size_t)2 * NN2);
    k_pad_w_t<false><<<(128 * FPK + 255) / 256, 256>>>(dgw, pWgd, 128);
    k_pad_w_t<false><<<(64 * FPK + 255) / 256, 256>>>(duw, pWud, 64);

    // ---- encoder
    for (int t = 0; t < Tt; t++) {
        k_set_x_enc<<<256, 256>>>(x, t);
        mma_gemm<256,128,0,3,512><<<dim3(33, 8), 512, SMEM_DIFF>>>(pSeh, pX, Nn, Nn, 1024, nullptr);
        mma_gemm<128,128,1,2,256><<<dim3(1, 512), 256, SMEM_GATE>>>(pF, pWge, FPK, FPK, 256, egb);
        mma_gemm<256,128,0,3,512><<<dim3(33, 8), 512, SMEM_DIFF>>>(pSeh, pX, Nn, Nn, 1024, nullptr);
        mma_gemm<128,64,2,2,256><<<dim3(1, 512), 256, SMEM_UPD>>>(pF, pWue, FPK, FPK, 256, eub);
    }

    // ---- decoder supports
    k_demb<<<ROWS * Ee / 256, 256>>>(fce);
    k_transpose<<<(ROWS * Ee + 255) / 256, 256>>>(pDemb, pDembT, Nn, Bb * Ee);
    sgemm32<<<dim3(16, 8), 256>>>(pDemb, pDembT, pSd, Nn, Nn, Bb * Ee);
    k_relu_softmax<<<Nn, 256>>>(pSd);
    sgemm32<<<dim3(16, 8), 256>>>(pSd, pSd, pSd + NN2, Nn, Nn, Nn);
    k_cheb<<<NN2 / 256, 256>>>(pSd + NN2);
    k_tohalf<<<2 * NN2 / 256, 256>>>(pSd, pSdh, (size_t)2 * NN2);
    k_init_go<<<256, 256>>>(x);

    // ---- decoder
    for (int t = 0; t < Hor; t++) {
        k_set_xy_dec<<<256, 256>>>(ycov, t);
        mma_gemm<256,128,0,3,512><<<dim3(33, 8), 512, SMEM_DIFF>>>(pSdh, pX, Nn, Nn, 1024, nullptr);
        mma_gemm<128,128,1,2,256><<<dim3(1, 512), 256, SMEM_GATE>>>(pF, pWgd, FPK, FPK, 256, dgb);
        mma_gemm<256,128,0,3,512><<<dim3(33, 8), 512, SMEM_DIFF>>>(pSdh, pX, Nn, Nn, 1024, nullptr);
        mma_gemm<128,64,2,2,256><<<dim3(1, 512), 256, SMEM_UPD>>>(pF, pWud, FPK, FPK, 256, dub);
        k_proj_out<<<256, 256>>>(pw, pb, out, t);
    }
}

// round 17
// speedup vs baseline: 1.0088x; 1.0088x over previous
#include <cuda_runtime.h>
#include <cuda_fp16.h>
#include <cstdint>
#include <math.h>

constexpr int Bb=64, Tt=12, Nn=1024, Ee=10, Hor=12;
constexpr int ROWS = Nn*Bb;          // 65536
constexpr int NN2  = Nn*Nn;
constexpr int FPK  = 256;            // padded K width of F (3*66=198 -> 256)
constexpr int XTC  = 66*Bb;          // 4224
// ROW ORDER: id = b*1024 + n  (batch-major)

// ---------------- device-global scratch ----------------
__device__ __align__(1024) float g_S_enc[2*NN2];
__device__ __align__(1024) float g_S_dec[2*NN2];
__device__ __align__(1024) __half g_Rh[(size_t)ROWS*64];   // r gate, fp16
__device__ __align__(1024) float g_h [(size_t)ROWS*64];
__device__ __align__(1024) float g_go[ROWS];
__device__ __align__(1024) float g_demb [Nn*Bb*Ee];
__device__ __align__(1024) float g_dembT[Bb*Ee*Nn];
__device__ __align__(1024) float g_embpad [Nn*16];
__device__ __align__(1024) float g_embpadT[16*Nn];

__device__ __align__(1024) __half g_Se_hi[2*NN2];
__device__ __align__(1024) __half g_Sd_hi[2*NN2];
__device__ __align__(1024) __half g_XT[(size_t)XTC*Nn];          // [b*66+c][n]
__device__ __align__(1024) __half g_F[(size_t)ROWS*FPK];         // [b*1024+n][256]
__device__ __align__(1024) __half g_Wge[128*FPK];
__device__ __align__(1024) __half g_Wue[64*FPK];
__device__ __align__(1024) __half g_Wgd[128*FPK];
__device__ __align__(1024) __half g_Wud[64*FPK];

// HW MUFU.TANH (sm_75+)
__device__ __forceinline__ float tanh_fast(float x){
    float y; asm("tanh.approx.f32 %0, %1;" : "=f"(y) : "f"(x)); return y;
}
__device__ __forceinline__ float sigmoid_fast(float x){
    return fmaf(0.5f, tanh_fast(0.5f * x), 0.5f);
}

__device__ __forceinline__ uint32_t smem_u32(const void* p){
    uint32_t a;
    asm("{ .reg .u64 t; cvta.to.shared.u64 t, %1; cvt.u32.u64 %0, t; }" : "=r"(a) : "l"(p));
    return a;
}
__device__ __forceinline__ void cp_async16(uint32_t dst, const void* src){
    asm volatile("cp.async.cg.shared.global [%0], [%1], 16;" :: "r"(dst), "l"(src));
}
__device__ __forceinline__ void cp_commit(){ asm volatile("cp.async.commit_group;"); }
template <int N>
__device__ __forceinline__ void cp_wait(){ asm volatile("cp.async.wait_group %0;" :: "n"(N)); }

__device__ __forceinline__ void ldsm_x4(uint32_t* r, uint32_t addr){
    asm volatile("ldmatrix.sync.aligned.m8n8.x4.shared.b16 {%0,%1,%2,%3}, [%4];"
        : "=r"(r[0]), "=r"(r[1]), "=r"(r[2]), "=r"(r[3]) : "r"(addr));
}
__device__ __forceinline__ void mma16816(float* c, const uint32_t* a, const uint32_t* b){
    asm volatile("mma.sync.aligned.m16n8k16.row.col.f32.f16.f16.f32 "
        "{%0,%1,%2,%3}, {%4,%5,%6,%7}, {%8,%9}, {%0,%1,%2,%3};"
        : "+f"(c[0]), "+f"(c[1]), "+f"(c[2]), "+f"(c[3])
        : "r"(a[0]), "r"(a[1]), "r"(a[2]), "r"(a[3]), "r"(b[0]), "r"(b[1]));
}

// ---------------- fp16 HMMA GEMM -----------------------
// D[M rows, N=BN per block] = A(M x segK) @ B^T, fp32 accumulate.
// A rows = output rows (lda); B rows = output COLUMNS, K-major (ldb).
// BM=128, BK=64, 256 threads (8 warps, 4m x 2n). Row id = b*1024+n.
// compute(): ks-level register double-buffering of ldsm fragments to break
// the ldsm->mma RAW chain (tensor pipe was 43% with issue 17.5%).
// NSTG=3: 3-stage pipeline (diffusion, KT=16).
// NSTG=2: 2-stage + cp.async prefetch of epilogue operands (MLPs, KT=4).
// EPI 0: diffusion -> fp16 scatter into g_F
// EPI 1: gate: z=sig(+bias), c<64 -> z*h into g_XT + g_F; c>=64 -> g_Rh
// EPI 2: update: hc=tanh(+bias); hn = r*h + (1-r)*hc -> g_h, g_XT, g_F
template <int BN, int EPI, int NSTG>
__global__ void __launch_bounds__(256, 2) mma_gemm(
    const __half* __restrict__ A, const __half* __restrict__ B,
    int lda, int ldb, int segK, const float* __restrict__ bias)
{
    constexpr int BM = 128, LDS = 72;      // 64 + 8 pad (half elems)
    constexpr int NT = BN / 16;
    constexpr uint32_t STG_BYTES = (uint32_t)(BM + BN) * LDS * 2u;
    extern __shared__ __align__(16) char sm[];
    const uint32_t sm0 = smem_u32(sm);

    const int tid = threadIdx.x, lane = tid & 31, wid = tid >> 5;
    const int wm = wid >> 1, wn = wid & 1;
    const int m0 = blockIdx.y * BM, n0 = blockIdx.x * BN;
    const int KT = segK >> 6;

    float acc[2][NT][4];
#pragma unroll
    for (int i = 0; i < 2; i++)
#pragma unroll
        for (int j = 0; j < NT; j++)
#pragma unroll
            for (int e = 0; e < 4; e++) acc[i][j][e] = 0.0f;

    const uint32_t aOff = (((uint32_t)(wm*32 + (lane & 15))) * LDS + ((lane >> 4) << 3)) * 2u;
    const uint32_t bOff = (uint32_t)BM * LDS * 2u
        + (((uint32_t)(wn*(BN/2) + (lane & 7) + ((lane >> 4) << 3))) * LDS
           + (((lane >> 3) & 1) << 3)) * 2u;

    auto load_tile = [&](int kt, int stg) {
        const uint32_t sA = sm0 + (uint32_t)stg * STG_BYTES;
        const uint32_t sB = sA + (uint32_t)BM * LDS * 2u;
        const char* Ag = (const char*)(A + (size_t)m0 * lda + kt * 64);
        const char* Bg = (const char*)(B + (size_t)n0 * ldb + kt * 64);
#pragma unroll
        for (int it = 0; it < 4; it++) {
            int id = (it << 8) + tid;
            int r = id >> 3, c = id & 7;
            cp_async16(sA + (uint32_t)r*144u + (uint32_t)c*16u,
                       Ag + (size_t)r * ((size_t)lda*2) + c*16);
        }
#pragma unroll
        for (int it = 0; it < BN/32; it++) {
            int id = (it << 8) + tid;
            int r = id >> 3, c = id & 7;
            cp_async16(sB + (uint32_t)r*144u + (uint32_t)c*16u,
                       Bg + (size_t)r * ((size_t)ldb*2) + c*16);
        }
        cp_commit();
    };

    // ks-pipelined compute: prefetch fragments for ks+1 while issuing ks mmas
    auto compute = [&](int stg) {
        const uint32_t sbase = sm0 + (uint32_t)stg * STG_BYTES;
        const uint32_t aBase = sbase + aOff;
        const uint32_t bBase = sbase + bOff;
        uint32_t a[2][2][4];
        uint32_t b[2][NT/2][4];
        ldsm_x4(a[0][0], aBase);
        ldsm_x4(a[0][1], aBase + 16u*LDS*2u);
#pragma unroll
        for (int p = 0; p < NT/2; p++)
            ldsm_x4(b[0][p], bBase + (uint32_t)p*16u*LDS*2u);
#pragma unroll
        for (int ks = 0; ks < 4; ks++) {
            const int cur = ks & 1, nxt = cur ^ 1;
            if (ks < 3) {
                ldsm_x4(a[nxt][0], aBase + (uint32_t)(ks+1)*32u);
                ldsm_x4(a[nxt][1], aBase + 16u*LDS*2u + (uint32_t)(ks+1)*32u);
#pragma unroll
                for (int p = 0; p < NT/2; p++)
                    ldsm_x4(b[nxt][p], bBase + (uint32_t)p*16u*LDS*2u + (uint32_t)(ks+1)*32u);
            }
#pragma unroll
            for (int mt = 0; mt < 2; mt++)
#pragma unroll
                for (int nt = 0; nt < NT; nt++)
                    mma16816(acc[mt][nt], a[cur][mt], &b[cur][nt >> 1][(nt & 1) * 2]);
        }
    };

    if (NSTG == 3) {
        load_tile(0, 0);
        if (KT > 1) load_tile(1, 1);
        int stg = 0;
        for (int kt = 0; kt < KT; kt++) {
            if (kt + 1 < KT) cp_wait<1>(); else cp_wait<0>();
            __syncthreads();
            if (kt + 2 < KT) load_tile(kt + 2, (kt + 2) % 3);
            compute(stg);
            if (++stg == 3) stg = 0;
        }
    } else {
        // prefetch epilogue operands under the mainloop
        if (EPI >= 1) {
#pragma unroll
            for (int it = 0; it < 8; it++) {
                int idx = (it << 8) + tid;
                cp_async16(sm0 + 2u*STG_BYTES + (uint32_t)idx*16u,
                           (const char*)g_h + (size_t)m0*256 + (size_t)idx*16);
            }
            if (EPI == 2) {
#pragma unroll
                for (int it = 0; it < 4; it++) {
                    int idx = (it << 8) + tid;
                    cp_async16(sm0 + 2u*STG_BYTES + 32768u + (uint32_t)idx*16u,
                               (const char*)g_Rh + (size_t)m0*128 + (size_t)idx*16);
                }
            }
            cp_commit();
        }
        load_tile(0, 0);
        for (int kt = 0; kt < KT; kt++) {
            cp_wait<0>();
            __syncthreads();
            if (kt + 1 < KT) load_tile(kt + 1, (kt + 1) & 1);
            compute(kt & 1);
        }
    }

    // ---------------- epilogue (paired half2/float2; batch-major rows) -------
    const float*  s_hf = reinterpret_cast<const float*>(sm + 2u*STG_BYTES);
    const __half* s_rh = reinterpret_cast<const __half*>(sm + 2u*STG_BYTES + 32768u);
    const int rbase = m0 + wm*32 + (lane >> 2);
    const int cb = n0 + wn*(BN/2) + ((lane & 3) << 1);   // even
#pragma unroll
    for (int mt = 0; mt < 2; mt++) {
#pragma unroll
        for (int nt = 0; nt < NT; nt++) {
#pragma unroll
            for (int ep = 0; ep < 2; ep++) {
                const int row = rbase + mt*16 + ep*8;
                const int lrow = row - m0;
                const int col0 = cb + nt*8;              // even
                const float v0 = acc[mt][nt][ep*2 + 0];
                const float v1 = acc[mt][nt][ep*2 + 1];
                if (EPI == 0) {
                    const int kk = row >> 10, n = row & 1023;
                    const int b = col0 / 66, c = col0 - b * 66;
                    const size_t off = (size_t)((b << 10) + n) * FPK + (kk + 1) * 66 + c;
                    *reinterpret_cast<__half2*>(&g_F[off]) = __floats2half2_rn(v0, v1);
                } else if (EPI == 1) {
                    const int id = row, b = row >> 10, n = row & 1023;
                    if (col0 < 64) {                      // warp-uniform (wn==0)
                        const float2 hp = *reinterpret_cast<const float2*>(
                            &s_hf[lrow * 64 + col0]);
                        const float zh0 = sigmoid_fast(v0 + bias[col0])     * hp.x;
                        const float zh1 = sigmoid_fast(v1 + bias[col0 + 1]) * hp.y;
                        const __half h0 = __float2half_rn(zh0);
                        const __half h1 = __float2half_rn(zh1);
                        g_XT[((size_t)(b * 66 + 2 + col0) << 10) + n] = h0;
                        g_XT[((size_t)(b * 66 + 3 + col0) << 10) + n] = h1;
                        *reinterpret_cast<__half2*>(&g_F[((size_t)id << 8) + 2 + col0]) =
                            __halves2half2(h0, h1);
                    } else {                              // warp-uniform (wn==1)
                        const float r0 = sigmoid_fast(v0 + bias[col0]);
                        const float r1 = sigmoid_fast(v1 + bias[col0 + 1]);
                        *reinterpret_cast<__half2*>(&g_Rh[(size_t)id * 64 + (col0 - 64)]) =
                            __floats2half2_rn(r0, r1);
                    }
                } else {
                    const int id = row, b = row >> 10, n = row & 1023;
                    const float2 hp = *reinterpret_cast<const float2*>(
                        &s_hf[lrow * 64 + col0]);
                    const __half2 rh = *reinterpret_cast<const __half2*>(
                        &s_rh[lrow * 64 + col0]);
                    const float2 rp = __half22float2(rh);
                    const float hc0 = tanh_fast(v0 + bias[col0]);
                    const float hc1 = tanh_fast(v1 + bias[col0 + 1]);
                    const float hn0 = rp.x * hp.x + (1.0f - rp.x) * hc0;
                    const float hn1 = rp.y * hp.y + (1.0f - rp.y) * hc1;
                    *reinterpret_cast<float2*>(&g_h[(size_t)id * 64 + col0]) =
                        make_float2(hn0, hn1);
                    const __half h0 = __float2half_rn(hn0);
                    const __half h1 = __float2half_rn(hn1);
                    g_XT[((size_t)(b * 66 + 2 + col0) << 10) + n] = h0;
                    g_XT[((size_t)(b * 66 + 3 + col0) << 10) + n] = h1;
                    *reinterpret_cast<__half2*>(&g_F[((size_t)id << 8) + 2 + col0]) =
                        __halves2half2(h0, h1);
                }
            }
        }
    }
}

// ---------------- fp32 SGEMM (setup only) ----------------
__global__ void __launch_bounds__(256) sgemm32(
    const float* __restrict__ A, const float* __restrict__ B,
    float* __restrict__ C, int M, int N, int K)
{
    constexpr int BM = 128, BN = 64, BK = 16;
    __shared__ __align__(16) float As_[BK][BM];
    __shared__ __align__(16) float Bs_[BK][BN];
    const int tid = threadIdx.x;
    const int tx = tid & 15, ty = tid >> 4;
    const int m0 = blockIdx.y * BM, n0 = blockIdx.x * BN;
    float acc[8][4];
#pragma unroll
    for (int i = 0; i < 8; i++)
#pragma unroll
        for (int jj = 0; jj < 4; jj++) acc[i][jj] = 0.0f;
    const int arow0 = tid >> 2, acol0 = (tid & 3) * 4;
    const int brow = tid >> 4, bcol = (tid & 15) * 4;
    for (int kt = 0; kt < K; kt += BK) {
#pragma unroll
        for (int i = 0; i < 2; i++) {
            int r = arow0 + i * 64;
            float4 v = *reinterpret_cast<const float4*>(A + (size_t)(m0 + r) * K + kt + acol0);
            As_[acol0+0][r]=v.x; As_[acol0+1][r]=v.y; As_[acol0+2][r]=v.z; As_[acol0+3][r]=v.w;
        }
        float4 bv = *reinterpret_cast<const float4*>(B + (size_t)(kt + brow) * N + n0 + bcol);
        *reinterpret_cast<float4*>(&Bs_[brow][bcol]) = bv;
        __syncthreads();
#pragma unroll
        for (int k = 0; k < BK; k++) {
            float4 a0 = *reinterpret_cast<const float4*>(&As_[k][ty*8]);
            float4 a1 = *reinterpret_cast<const float4*>(&As_[k][ty*8+4]);
            float4 b0 = *reinterpret_cast<const float4*>(&Bs_[k][tx*4]);
            float am[8]={a0.x,a0.y,a0.z,a0.w,a1.x,a1.y,a1.z,a1.w};
            float bn[4]={b0.x,b0.y,b0.z,b0.w};
#pragma unroll
            for (int i = 0; i < 8; i++)
#pragma unroll
                for (int jj = 0; jj < 4; jj++) acc[i][jj] = fmaf(am[i], bn[jj], acc[i][jj]);
        }
        __syncthreads();
    }
#pragma unroll
    for (int i = 0; i < 8; i++) {
        float4 v = make_float4(acc[i][0], acc[i][1], acc[i][2], acc[i][3]);
        *reinterpret_cast<float4*>(C + (size_t)(m0 + ty*8 + i) * N + n0 + tx*4) = v;
    }
}

// ---------------- elementwise helpers (id = b*1024 + n) ----------------
__global__ void k_zero_state() {
    int idx = blockIdx.x * blockDim.x + threadIdx.x;
    if (idx >= ROWS * 64) return;
    int id = idx >> 6, i = idx & 63;
    int b = id >> 10, n = id & 1023;
    g_h[idx] = 0.0f;
    g_XT[((size_t)(b * 66 + 2 + i) << 10) + n] = __float2half_rn(0.0f);
    g_F[((size_t)id << 8) + 2 + i] = __float2half_rn(0.0f);
}
__global__ void k_tohalf(const float* __restrict__ s, __half* __restrict__ hi, size_t n) {
    size_t i = (size_t)blockIdx.x * blockDim.x + threadIdx.x;
    if (i >= n) return;
    hi[i] = __float2half_rn(s[i]);
}
__global__ void k_pad_emb(const float* __restrict__ emb) {
    int idx = blockIdx.x * blockDim.x + threadIdx.x;
    if (idx >= Nn * 16) return;
    int n = idx >> 4, j = idx & 15;
    g_embpad[idx] = (j < Ee) ? emb[n * Ee + j] : 0.0f;
}
__global__ void k_transpose(const float* __restrict__ in, float* __restrict__ out,
                            int R, int C) {
    int idx = blockIdx.x * blockDim.x + threadIdx.x;
    if (idx >= R * C) return;
    int r = idx / C, c = idx - r * C;
    out[c * R + r] = in[idx];
}
template <bool ENC>
__global__ void k_pad_w_t(const float* __restrict__ src, __half* __restrict__ dst,
                          int nout) {
    int idx = blockIdx.x * blockDim.x + threadIdx.x;
    if (idx >= nout * FPK) return;
    int n = idx >> 8, f = idx & 255;
    float v = 0.0f;
    if (f < 198) {
        int k = f / 66, c = f - k * 66;
        if (ENC) {
            if (c == 0) v = src[(k * 65) * nout + n];
            else if (c >= 2) v = src[(k * 65 + c - 1) * nout + n];
        } else {
            v = src[f * nout + n];
        }
    }
    dst[idx] = __float2half_rn(v);
}
__global__ void k_relu_softmax(float* __restrict__ S) {
    int row = blockIdx.x;
    float* p = S + (size_t)row * Nn;
    int t = threadIdx.x;
    float v[4];
#pragma unroll
    for (int i = 0; i < 4; i++) { float x = p[t + i*256]; v[i] = x > 0.0f ? x : 0.0f; }
    __shared__ float red[256];
    float m = fmaxf(fmaxf(v[0], v[1]), fmaxf(v[2], v[3]));
    red[t] = m; __syncthreads();
    for (int s = 128; s > 0; s >>= 1) { if (t < s) red[t] = fmaxf(red[t], red[t+s]); __syncthreads(); }
    m = red[0]; __syncthreads();
    float e[4], sum = 0.0f;
#pragma unroll
    for (int i = 0; i < 4; i++) { e[i] = expf(v[i] - m); sum += e[i]; }
    red[t] = sum; __syncthreads();
    for (int s = 128; s > 0; s >>= 1) { if (t < s) red[t] += red[t+s]; __syncthreads(); }
    float inv = 1.0f / red[0];
#pragma unroll
    for (int i = 0; i < 4; i++) p[t + i*256] = e[i] * inv;
}
__global__ void k_cheb(float* __restrict__ P) {
    int idx = blockIdx.x * blockDim.x + threadIdx.x;
    if (idx >= NN2) return;
    int r = idx >> 10, c = idx & 1023;
    P[idx] = 2.0f * P[idx] - (r == c ? 1.0f : 0.0f);
}
__global__ void k_set_x_enc(const float* __restrict__ x, int t) {
    int id = blockIdx.x * blockDim.x + threadIdx.x;
    if (id >= ROWS) return;
    int b = id >> 10, n = id & 1023;
    float xv = x[((size_t)b * Tt + t) * Nn + n];
    __half xh = __float2half_rn(xv);
    g_XT[((size_t)(b * 66) << 10) + n] = xh;
    g_F[(size_t)id << 8] = xh;
}
__global__ void k_set_xy_dec(const float* __restrict__ ycov, int t) {
    int id = blockIdx.x * blockDim.x + threadIdx.x;
    if (id >= ROWS) return;
    int b = id >> 10, n = id & 1023;
    float gv = g_go[id];
    float yv = ycov[((size_t)b * Hor + t) * Nn + n];
    __half gh = __float2half_rn(gv);
    __half yh = __float2half_rn(yv);
    g_XT[((size_t)(b * 66) << 10) + n] = gh;
    g_XT[((size_t)(b * 66 + 1) << 10) + n] = yh;
    size_t fo = (size_t)id << 8;
    g_F[fo] = gh;
    g_F[fo + 1] = yh;
}
__global__ void k_demb(const float* __restrict__ fce) {
    int idx = blockIdx.x * blockDim.x + threadIdx.x;
    if (idx >= ROWS * Ee) return;
    int id = idx / Ee, e = idx - id * Ee;
    int b = id >> 10, n = id & 1023;
    const float* hr = g_h + (size_t)id * 64;
    float s = 0.0f;
#pragma unroll
    for (int h = 0; h < 64; h++) s = fmaf(hr[h], fce[h * Ee + e], s);
    g_demb[(size_t)n * (Bb * Ee) + b * Ee + e] = s;
}
__global__ void k_init_go(const float* __restrict__ x) {
    int id = blockIdx.x * blockDim.x + threadIdx.x;
    if (id >= ROWS) return;
    int b = id >> 10, n = id & 1023;
    g_go[id] = x[((size_t)b * Tt + (Tt - 1)) * Nn + n];
}
__global__ void k_proj_out(const float* __restrict__ pw, const float* __restrict__ pb,
                           float* __restrict__ out, int t) {
    int id = blockIdx.x * blockDim.x + threadIdx.x;
    if (id >= ROWS) return;
    int b = id >> 10, n = id & 1023;
    const float* hr = g_h + (size_t)id * 64;
    float s = pb[0];
#pragma unroll
    for (int i = 0; i < 64; i++) s = fmaf(hr[i], pw[i], s);
    g_go[id] = s;
    out[((size_t)b * Hor + t) * Nn + n] = s;
}

// ---------------- orchestration ----------------
extern "C" void kernel_launch(void* const* d_in, const int* in_sizes, int n_in,
                              void* d_out, int out_size) {
    const float* x    = (const float*)d_in[0];
    const float* ycov = (const float*)d_in[1];
    const float* emb  = (const float*)d_in[2];
    const float* fce  = (const float*)d_in[3];
    const float* egw  = (const float*)d_in[4];
    const float* egb  = (const float*)d_in[5];
    const float* euw  = (const float*)d_in[6];
    const float* eub  = (const float*)d_in[7];
    const float* dgw  = (const float*)d_in[8];
    const float* dgb  = (const float*)d_in[9];
    const float* duw  = (const float*)d_in[10];
    const float* dub  = (const float*)d_in[11];
    const float* pw   = (const float*)d_in[12];
    const float* pb   = (const float*)d_in[13];
    float* out = (float*)d_out;

    float *pSe, *pSd, *pDemb, *pDembT, *pEp, *pEpT;
    __half *pSeh, *pSdh, *pX, *pF, *pWge, *pWue, *pWgd, *pWud;
    cudaGetSymbolAddress((void**)&pSe, g_S_enc);
    cudaGetSymbolAddress((void**)&pSd, g_S_dec);
    cudaGetSymbolAddress((void**)&pDemb, g_demb);
    cudaGetSymbolAddress((void**)&pDembT, g_dembT);
    cudaGetSymbolAddress((void**)&pEp, g_embpad);
    cudaGetSymbolAddress((void**)&pEpT, g_embpadT);
    cudaGetSymbolAddress((void**)&pSeh, g_Se_hi);
    cudaGetSymbolAddress((void**)&pSdh, g_Sd_hi);
    cudaGetSymbolAddress((void**)&pX, g_XT);
    cudaGetSymbolAddress((void**)&pF, g_F);
    cudaGetSymbolAddress((void**)&pWge, g_Wge);
    cudaGetSymbolAddress((void**)&pWue, g_Wue);
    cudaGetSymbolAddress((void**)&pWgd, g_Wgd);
    cudaGetSymbolAddress((void**)&pWud, g_Wud);

    constexpr int SMEM_DIFF = 3 * (128 + 128) * 72 * 2;                 // 110592
    constexpr int SMEM_GATE = 2 * (128 + 128) * 72 * 2 + 32768;         // 106496
    constexpr int SMEM_UPD  = 2 * (128 + 64) * 72 * 2 + 32768 + 16384;  // 104448
    cudaFuncSetAttribute(mma_gemm<128,0,3>, cudaFuncAttributeMaxDynamicSharedMemorySize, SMEM_DIFF);
    cudaFuncSetAttribute(mma_gemm<128,1,2>, cudaFuncAttributeMaxDynamicSharedMemorySize, SMEM_GATE);
    cudaFuncSetAttribute(mma_gemm<64,2,2>,  cudaFuncAttributeMaxDynamicSharedMemorySize, SMEM_UPD);

    // ---- setup; launch index 3 (0-based) == diffusion GEMM for ncu
    k_zero_state<<<16384, 256>>>();                                                     // 0
    k_pad_w_t<true><<<(128 * FPK + 255) / 256, 256>>>(egw, pWge, 128);                  // 1
    k_pad_w_t<true><<<(64 * FPK + 255) / 256, 256>>>(euw, pWue, 64);                    // 2
    // ncu target: real-shape diffusion (deterministic inputs; F cols 66..197
    // overwritten by the real t=0 diffusion before any consumer)
    mma_gemm<128,0,3><<<dim3(33, 16), 256, SMEM_DIFF>>>(pSeh, pX, Nn, Nn, 1024, nullptr); // 3
    k_pad_emb<<<64, 256>>>(emb);
    k_transpose<<<64, 256>>>(pEp, pEpT, Nn, 16);
    sgemm32<<<dim3(16, 8), 256>>>(pEp, pEpT, pSe, Nn, Nn, 16);
    k_relu_softmax<<<Nn, 256>>>(pSe);
    sgemm32<<<dim3(16, 8), 256>>>(pSe, pSe, pSe + NN2, Nn, Nn, Nn);
    k_cheb<<<NN2 / 256, 256>>>(pSe + NN2);
    k_tohalf<<<2 * NN2 / 256, 256>>>(pSe, pSeh, (size_t)2 * NN2);
    k_pad_w_t<false><<<(128 * FPK + 255) / 256, 256>>>(dgw, pWgd, 128);
    k_pad_w_t<false><<<(64 * FPK + 255) / 256, 256>>>(duw, pWud, 64);

    // ---- encoder
    for (int t = 0; t < Tt; t++) {
        k_set_x_enc<<<256, 256>>>(x, t);
        mma_gemm<128,0,3><<<dim3(33, 16), 256, SMEM_DIFF>>>(pSeh, pX, Nn, Nn, 1024, nullptr);
        mma_gemm<128,1,2><<<dim3(1, 512), 256, SMEM_GATE>>>(pF, pWge, FPK, FPK, 256, egb);
        mma_gemm<128,0,3><<<dim3(33, 16), 256, SMEM_DIFF>>>(pSeh, pX, Nn, Nn, 1024, nullptr);
        mma_gemm<64,2,2><<<dim3(1, 512), 256, SMEM_UPD>>>(pF, pWue, FPK, FPK, 256, eub);
    }

    // ---- decoder supports
    k_demb<<<ROWS * Ee / 256, 256>>>(fce);
    k_transpose<<<(ROWS * Ee + 255) / 256, 256>>>(pDemb, pDembT, Nn, Bb * Ee);
    sgemm32<<<dim3(16, 8), 256>>>(pDemb, pDembT, pSd, Nn, Nn, Bb * Ee);
    k_relu_softmax<<<Nn, 256>>>(pSd);
    sgemm32<<<dim3(16, 8), 256>>>(pSd, pSd, pSd + NN2, Nn, Nn, Nn);
    k_cheb<<<NN2 / 256, 256>>>(pSd + NN2);
    k_tohalf<<<2 * NN2 / 256, 256>>>(pSd, pSdh, (size_t)2 * NN2);
    k_init_go<<<256, 256>>>(x);

    // ---- decoder
    for (int t = 0; t < Hor; t++) {
        k_set_xy_dec<<<256, 256>>>(ycov, t);
        mma_gemm<128,0,3><<<dim3(33, 16), 256, SMEM_DIFF>>>(pSdh, pX, Nn, Nn, 1024, nullptr);
        mma_gemm<128,1,2><<<dim3(1, 512), 256, SMEM_GATE>>>(pF, pWgd, FPK, FPK, 256, dgb);
        mma_gemm<128,0,3><<<dim3(33, 16), 256, SMEM_DIFF>>>(pSdh, pX, Nn, Nn, 1024, nullptr);
        mma_gemm<64,2,2><<<dim3(1, 512), 256, SMEM_UPD>>>(pF, pWud, FPK, FPK, 256, dub);
        k_proj_out<<<256, 256>>>(pw, pb, out, t);
    }
}